// round 1
// baseline (speedup 1.0000x reference)
#include <cuda_runtime.h>

// Problem constants
#define B_   4
#define L_   256
#define E_   256
#define F_   256
#define K3_  768
#define NL_  6

// Scratch: conv features out[b][l][768] (k=2 filters at 0..255, k=3 at 256..511, k=4 at 512..767)
__device__ float g_feat[B_ * L_ * K3_];

// ---------------------------------------------------------------------------
// Conv stage: one CTA computes a 64(l) x 64(f) tile of one conv kind.
// Inner K-dim = E (256), chunked by 16. A (embeddings w/ halo) and B (weights)
// staged in shared memory; 4x4 register tile per thread (256 threads).
// ---------------------------------------------------------------------------
template<int K, int PAD>
__device__ __forceinline__ void conv_body(
    const int* __restrict__ sIds,
    float (*As)[68],            // [e][row], rows = l0-1 .. l0+66
    float* __restrict__ Bs,     // [e][t][f] flattened: (e*K + t)*64 + f
    const float* __restrict__ emb,
    const float* __restrict__ w,
    const float* __restrict__ bias,
    int b, int l0, int obase, int fbase, int tid)
{
    const int ti = tid >> 4;     // 0..15: row group (4 rows each)
    const int tj = tid & 15;     // 0..15: col group (4 cols each)

    float acc[4][4] = {};

    for (int e0 = 0; e0 < E_; e0 += 16) {
        // --- load A: 16 e x 68 rows, gathered through embedding table ---
        for (int idx = tid; idx < 16 * 68; idx += 256) {
            int r = idx >> 4;
            int e = idx & 15;
            int id = sIds[r];
            As[e][r] = (id >= 0) ? emb[id * E_ + e0 + e] : 0.0f;
        }
        // --- load B: 16 e x K taps x 64 f ---
        for (int idx = tid; idx < 16 * K * 64; idx += 256) {
            int f = idx & 63;
            int rem = idx >> 6;          // 0 .. 16*K-1, e-major over (e,t)
            int t = rem % K;
            int e = rem / K;
            Bs[(e * K + t) * 64 + f] = w[((obase + f) * E_ + (e0 + e)) * K + t];
        }
        __syncthreads();

        #pragma unroll
        for (int e = 0; e < 16; e++) {
            float a[K + 3];
            #pragma unroll
            for (int m = 0; m < K + 3; m++)
                a[m] = As[e][4 * ti + (1 - PAD) + m];
            #pragma unroll
            for (int t = 0; t < K; t++) {
                const float4 bv = *reinterpret_cast<const float4*>(
                    &Bs[(e * K + t) * 64 + 4 * tj]);
                #pragma unroll
                for (int il = 0; il < 4; il++) {
                    const float av = a[il + t];
                    acc[il][0] += av * bv.x;
                    acc[il][1] += av * bv.y;
                    acc[il][2] += av * bv.z;
                    acc[il][3] += av * bv.w;
                }
            }
        }
        __syncthreads();
    }

    // --- epilogue: add bias, store to g_feat ---
    const float bb0 = bias[obase + 4 * tj + 0];
    const float bb1 = bias[obase + 4 * tj + 1];
    const float bb2 = bias[obase + 4 * tj + 2];
    const float bb3 = bias[obase + 4 * tj + 3];
    #pragma unroll
    for (int il = 0; il < 4; il++) {
        int l = l0 + 4 * ti + il;
        float4 v;
        v.x = acc[il][0] + bb0;
        v.y = acc[il][1] + bb1;
        v.z = acc[il][2] + bb2;
        v.w = acc[il][3] + bb3;
        *reinterpret_cast<float4*>(
            &g_feat[(b * L_ + l) * K3_ + fbase + obase + 4 * tj]) = v;
    }
}

__global__ __launch_bounds__(256) void conv_all_kernel(
    const int* __restrict__ ids, const float* __restrict__ emb,
    const float* __restrict__ w2, const float* __restrict__ b2,
    const float* __restrict__ w3, const float* __restrict__ b3,
    const float* __restrict__ w4, const float* __restrict__ b4)
{
    __shared__ __align__(16) float As[16][68];
    __shared__ __align__(16) float Bs[16 * 4 * 64];
    __shared__ int sIds[68];

    const int l0    = blockIdx.x * 64;
    const int kind  = blockIdx.y >> 2;
    const int obase = (blockIdx.y & 3) * 64;
    const int b     = blockIdx.z;
    const int tid   = threadIdx.x;

    if (tid < 68) {
        int gl = l0 - 1 + tid;
        sIds[tid] = (gl >= 0 && gl < L_) ? ids[b * L_ + gl] : -1;
    }
    __syncthreads();

    if (kind == 0)      conv_body<2, 0>(sIds, As, Bs, emb, w2, b2, b, l0, obase, 0,   tid);
    else if (kind == 1) conv_body<3, 1>(sIds, As, Bs, emb, w3, b3, b, l0, obase, 256, tid);
    else                conv_body<4, 1>(sIds, As, Bs, emb, w4, b4, b, l0, obase, 512, tid);
}

// ---------------------------------------------------------------------------
// Pair stage: 28 GEMMs  C[i,j] = sum_k (feat[b,i,k]*w_c[k]) * feat[b,j,k].
// blockIdx.z = b*7 + c  (c in 0..5 -> triple label, c==6 -> score head)
// 64x64 CTA tile, 4x4 register tile, K=768 chunked by 16.
// ---------------------------------------------------------------------------
__global__ __launch_bounds__(256) void pair_kernel(
    const float* __restrict__ tw, const float* __restrict__ tb,
    const float* __restrict__ sw, const float* __restrict__ sb,
    float* __restrict__ out)
{
    const int bz = blockIdx.z;
    const int b  = bz / 7;
    const int c  = bz % 7;
    const int i0 = blockIdx.y * 64;
    const int j0 = blockIdx.x * 64;

    const float* __restrict__ wc = (c < 6) ? (tw + c * K3_) : sw;
    const float  bias = (c < 6) ? tb[c] : sb[0];
    const float* __restrict__ feat = g_feat + (size_t)b * L_ * K3_;

    __shared__ __align__(16) float As[16][68];   // [k][i], w-scaled
    __shared__ __align__(16) float Bs[16][68];   // [k][j]

    const int tid = threadIdx.x;
    const int ti = tid >> 4;
    const int tj = tid & 15;

    float acc[4][4] = {};

    for (int k0 = 0; k0 < K3_; k0 += 16) {
        for (int idx = tid; idx < 1024; idx += 256) {
            int r  = idx >> 4;
            int kk = idx & 15;
            float wv = __ldg(wc + k0 + kk);
            As[kk][r] = feat[(i0 + r) * K3_ + k0 + kk] * wv;
            Bs[kk][r] = feat[(j0 + r) * K3_ + k0 + kk];
        }
        __syncthreads();

        #pragma unroll
        for (int kk = 0; kk < 16; kk++) {
            const float4 av = *reinterpret_cast<const float4*>(&As[kk][4 * ti]);
            const float4 bv = *reinterpret_cast<const float4*>(&Bs[kk][4 * tj]);
            acc[0][0] += av.x * bv.x; acc[0][1] += av.x * bv.y;
            acc[0][2] += av.x * bv.z; acc[0][3] += av.x * bv.w;
            acc[1][0] += av.y * bv.x; acc[1][1] += av.y * bv.y;
            acc[1][2] += av.y * bv.z; acc[1][3] += av.y * bv.w;
            acc[2][0] += av.z * bv.x; acc[2][1] += av.z * bv.y;
            acc[2][2] += av.z * bv.z; acc[2][3] += av.z * bv.w;
            acc[3][0] += av.w * bv.x; acc[3][1] += av.w * bv.y;
            acc[3][2] += av.w * bv.z; acc[3][3] += av.w * bv.w;
        }
        __syncthreads();
    }

    if (c < 6) {
        #pragma unroll
        for (int il = 0; il < 4; il++) {
            const int i = i0 + 4 * ti + il;
            #pragma unroll
            for (int jl = 0; jl < 4; jl++) {
                const int j = j0 + 4 * tj + jl;
                out[(((b * L_ + i) * L_) + j) * NL_ + c] = acc[il][jl] + bias;
            }
        }
    } else {
        float* __restrict__ sc = out + (size_t)B_ * L_ * L_ * NL_;
        #pragma unroll
        for (int il = 0; il < 4; il++) {
            const int i = i0 + 4 * ti + il;
            #pragma unroll
            for (int jl = 0; jl < 4; jl++) {
                const int j = j0 + 4 * tj + jl;
                sc[(b * L_ + i) * L_ + j] = acc[il][jl] + bias;
            }
        }
    }
}

// ---------------------------------------------------------------------------
extern "C" void kernel_launch(void* const* d_in, const int* in_sizes, int n_in,
                              void* d_out, int out_size) {
    const int*   ids = (const int*)  d_in[0];
    const float* emb = (const float*)d_in[1];
    const float* w2  = (const float*)d_in[2];
    const float* b2  = (const float*)d_in[3];
    const float* w3  = (const float*)d_in[4];
    const float* b3  = (const float*)d_in[5];
    const float* w4  = (const float*)d_in[6];
    const float* b4  = (const float*)d_in[7];
    const float* tw  = (const float*)d_in[8];
    const float* tb  = (const float*)d_in[9];
    const float* sw  = (const float*)d_in[10];
    const float* sb  = (const float*)d_in[11];
    float* out = (float*)d_out;

    dim3 cgrid(L_ / 64, 12, B_);          // 4 l-tiles x (3 kinds * 4 f-tiles) x 4 batches
    conv_all_kernel<<<cgrid, 256>>>(ids, emb, w2, b2, w3, b3, w4, b4);

    dim3 pgrid(L_ / 64, L_ / 64, B_ * 7); // 4 x 4 x 28
    pair_kernel<<<pgrid, 256>>>(tw, tb, sw, sb, out);
}

// round 3
// speedup vs baseline: 2.2713x; 2.2713x over previous
#include <cuda_runtime.h>
#include <cuda_bf16.h>
#include <cstdint>

// Problem constants
#define B_   4
#define L_   256
#define E_   256
#define F_   256
#define K3_  768
#define NL_  6
#define MSTACK_ 1792   // 7 heads * 256 rows

// ---------------- scratch ----------------
__device__ __align__(16) float g_feat[B_ * L_ * K3_];          // conv output, fp32
__device__ __align__(16) float g_wr[589824];                   // reformatted conv weights [kind][e][t][f]
__device__ __align__(16) __nv_bfloat16 g_A[(size_t)B_ * MSTACK_ * K3_]; // weight-scaled feat, 7 heads stacked
__device__ __align__(16) __nv_bfloat16 g_B[(size_t)B_ * L_ * K3_];      // feat in bf16

#define W2OFF 0
#define W3OFF 131072
#define W4OFF 327680

// ---------------------------------------------------------------------------
// Kernel 1: reformat conv weights [f][e][t] -> [e*K+t][f] per kind (coalesced
// consumption by the conv kernel).
// ---------------------------------------------------------------------------
__global__ __launch_bounds__(256) void reformat_w_kernel(
    const float* __restrict__ w2, const float* __restrict__ w3,
    const float* __restrict__ w4)
{
    const int idx = blockIdx.x * 256 + threadIdx.x;  // over 65536 (f,e), e fastest
    const int e = idx & 255;
    const int f = idx >> 8;
    const int kind = blockIdx.y;
    const int K = kind + 2;
    const float* w = (kind == 0) ? w2 : (kind == 1) ? w3 : w4;
    const int off = (kind == 0) ? W2OFF : (kind == 1) ? W3OFF : W4OFF;
    for (int t = 0; t < K; t++)
        g_wr[off + (e * K + t) * 256 + f] = w[(f * 256 + e) * K + t];
}

// ---------------------------------------------------------------------------
// Kernel 2: conv. One CTA = 64(l) x 32(f) tile of one conv kind.
// ---------------------------------------------------------------------------
template<int K, int PAD>
__device__ __forceinline__ void conv_body(
    const int* __restrict__ sIds,
    float (*As)[68], float* __restrict__ Bs,
    const float* __restrict__ emb, const float* __restrict__ bias,
    int woff, int b, int l0, int obase, int fbase, int tid)
{
    const int ti = tid >> 4;     // 0..15 -> 4 l each
    const int tj = tid & 15;     // 0..15 -> 2 f each

    float acc[4][2] = {};

    for (int e0 = 0; e0 < E_; e0 += 16) {
        for (int idx = tid; idx < 16 * 68; idx += 256) {
            int r = idx >> 4;
            int e = idx & 15;
            int id = sIds[r];
            As[e][r] = (id >= 0) ? emb[id * E_ + e0 + e] : 0.0f;
        }
        for (int idx = tid; idx < 16 * K * 32; idx += 256) {
            int f   = idx & 31;
            int rem = idx >> 5;                 // rem = e*K + t
            Bs[rem * 32 + f] = g_wr[woff + (e0 * K + rem) * 256 + obase + f];
        }
        __syncthreads();

        #pragma unroll
        for (int e = 0; e < 16; e++) {
            float a[K + 3];
            #pragma unroll
            for (int m = 0; m < K + 3; m++)
                a[m] = As[e][4 * ti + (1 - PAD) + m];
            #pragma unroll
            for (int t = 0; t < K; t++) {
                const float2 bv = *reinterpret_cast<const float2*>(
                    &Bs[(e * K + t) * 32 + 2 * tj]);
                #pragma unroll
                for (int il = 0; il < 4; il++) {
                    acc[il][0] += a[il + t] * bv.x;
                    acc[il][1] += a[il + t] * bv.y;
                }
            }
        }
        __syncthreads();
    }

    const float bb0 = bias[obase + 2 * tj + 0];
    const float bb1 = bias[obase + 2 * tj + 1];
    #pragma unroll
    for (int il = 0; il < 4; il++) {
        int l = l0 + 4 * ti + il;
        float2 v = make_float2(acc[il][0] + bb0, acc[il][1] + bb1);
        *reinterpret_cast<float2*>(
            &g_feat[(b * L_ + l) * K3_ + fbase + obase + 2 * tj]) = v;
    }
}

__global__ __launch_bounds__(256) void conv_all_kernel(
    const int* __restrict__ ids, const float* __restrict__ emb,
    const float* __restrict__ b2, const float* __restrict__ b3,
    const float* __restrict__ b4)
{
    __shared__ __align__(16) float As[16][68];
    __shared__ __align__(16) float Bs[16 * 4 * 32];
    __shared__ int sIds[68];

    const int l0    = blockIdx.x * 64;
    const int kind  = blockIdx.y >> 3;
    const int obase = (blockIdx.y & 7) * 32;
    const int b     = blockIdx.z;
    const int tid   = threadIdx.x;

    if (tid < 68) {
        int gl = l0 - 1 + tid;
        sIds[tid] = (gl >= 0 && gl < L_) ? ids[b * L_ + gl] : -1;
    }
    __syncthreads();

    if (kind == 0)      conv_body<2, 0>(sIds, As, Bs, emb, b2, W2OFF, b, l0, obase, 0,   tid);
    else if (kind == 1) conv_body<3, 1>(sIds, As, Bs, emb, b3, W3OFF, b, l0, obase, 256, tid);
    else                conv_body<4, 1>(sIds, As, Bs, emb, b4, W4OFF, b, l0, obase, 512, tid);
}

// ---------------------------------------------------------------------------
// Kernel 3: build bf16 GEMM operands.
//   g_A[b][head*256+i][k] = bf16( feat[b][i][k] * w_head[k] )
//   g_B[b][j][k]          = bf16( feat[b][j][k] )
// ---------------------------------------------------------------------------
__global__ __launch_bounds__(256) void build_ab_kernel(
    const float* __restrict__ tw, const float* __restrict__ sw)
{
    const int g  = blockIdx.x * 256 + threadIdx.x;  // over 4*256*384, k-pair fastest
    const int kk = g % 384;
    const int rem = g / 384;
    const int i  = rem & 255;
    const int b  = rem >> 8;

    const float2 f2 = *reinterpret_cast<const float2*>(
        &g_feat[(b * L_ + i) * K3_ + 2 * kk]);

    *reinterpret_cast<__nv_bfloat162*>(
        &g_B[((size_t)(b * L_ + i)) * K3_ + 2 * kk]) =
        __float22bfloat162_rn(f2);

    #pragma unroll
    for (int h = 0; h < 7; h++) {
        const float* wc = (h < 6) ? (tw + h * K3_) : sw;
        const float2 w2v = *reinterpret_cast<const float2*>(&wc[2 * kk]);
        float2 p = make_float2(f2.x * w2v.x, f2.y * w2v.y);
        *reinterpret_cast<__nv_bfloat162*>(
            &g_A[((size_t)b * MSTACK_ + h * 256 + i) * K3_ + 2 * kk]) =
            __float22bfloat162_rn(p);
    }
}

// ---------------------------------------------------------------------------
// Kernel 4: pair GEMM on tensor cores.
//   per batch b: C[1792, 256] = A[1792, 768] * B[256, 768]^T   (row x row = NT)
//   CTA tile 128x128, 8 warps (2M x 4N), warp tile 64x32, mma.m16n8k16 bf16.
//   cp.async double-buffered K pipeline, K-chunk 32.
// ---------------------------------------------------------------------------
__device__ __forceinline__ void ldsm_x4(uint32_t* r, uint32_t addr) {
    asm volatile("ldmatrix.sync.aligned.m8n8.x4.shared.b16 {%0,%1,%2,%3}, [%4];"
        : "=r"(r[0]), "=r"(r[1]), "=r"(r[2]), "=r"(r[3]) : "r"(addr));
}
// B stored [n][k] row-major (k contiguous): the m16n8k16 B-fragment wants two
// consecutive k at fixed n per thread -> NON-transposed x2 load.
__device__ __forceinline__ void ldsm_x2(uint32_t* r, uint32_t addr) {
    asm volatile("ldmatrix.sync.aligned.m8n8.x2.shared.b16 {%0,%1}, [%2];"
        : "=r"(r[0]), "=r"(r[1]) : "r"(addr));
}
__device__ __forceinline__ void mma16816(float* c, const uint32_t* a, const uint32_t* b) {
    asm volatile("mma.sync.aligned.m16n8k16.row.col.f32.bf16.bf16.f32 "
        "{%0,%1,%2,%3}, {%4,%5,%6,%7}, {%8,%9}, {%0,%1,%2,%3};"
        : "+f"(c[0]), "+f"(c[1]), "+f"(c[2]), "+f"(c[3])
        : "r"(a[0]), "r"(a[1]), "r"(a[2]), "r"(a[3]), "r"(b[0]), "r"(b[1]));
}

#define SMS 40   // smem row stride (bf16 elems): 32 payload + 8 pad (80B, conflict-free)

__global__ __launch_bounds__(256) void pair_mma_kernel(
    const float* __restrict__ tb, const float* __restrict__ sb,
    float* __restrict__ out)
{
    __shared__ __align__(16) __nv_bfloat16 As[2][128 * SMS];
    __shared__ __align__(16) __nv_bfloat16 Bs[2][128 * SMS];

    const int tid  = threadIdx.x;
    const int lane = tid & 31;
    const int wid  = tid >> 5;
    const int wm   = (wid >> 2) * 64;   // 0 / 64
    const int wn   = (wid & 3) * 32;    // 0..96

    const int b  = blockIdx.z;
    const int m0 = blockIdx.x * 128;    // in 0..1791
    const int n0 = blockIdx.y * 128;

    const __nv_bfloat16* gA = g_A + ((size_t)b * MSTACK_ + m0) * K3_;
    const __nv_bfloat16* gB = g_B + ((size_t)b * L_ + n0) * K3_;

    float acc[4][4][4] = {};

    // --- async stage loader ---
    const int lrow = tid >> 2;
    const int lq   = tid & 3;

    auto load_stage = [&](int stage, int k0) {
        #pragma unroll
        for (int it = 0; it < 2; it++) {
            int row = lrow + it * 64;
            uint32_t sA = (uint32_t)__cvta_generic_to_shared(
                &As[stage][row * SMS + lq * 8]);
            const void* pA = gA + (size_t)row * K3_ + k0 + lq * 8;
            asm volatile("cp.async.cg.shared.global [%0], [%1], 16;" :: "r"(sA), "l"(pA));
            uint32_t sB = (uint32_t)__cvta_generic_to_shared(
                &Bs[stage][row * SMS + lq * 8]);
            const void* pB = gB + (size_t)row * K3_ + k0 + lq * 8;
            asm volatile("cp.async.cg.shared.global [%0], [%1], 16;" :: "r"(sB), "l"(pB));
        }
        asm volatile("cp.async.commit_group;");
    };

    load_stage(0, 0);

    const int arow = wm + (lane & 15);
    const int acol = (lane >> 4) * 8;
    const int brow = wn + (lane & 7);
    const int bcol = ((lane >> 3) & 1) * 8;

    for (int it = 0; it < 24; it++) {
        if (it < 23) load_stage((it + 1) & 1, (it + 1) * 32);

        if (it < 23) asm volatile("cp.async.wait_group 1;");
        else         asm volatile("cp.async.wait_group 0;");
        __syncthreads();

        const int st = it & 1;
        uint32_t aBase = (uint32_t)__cvta_generic_to_shared(&As[st][0]);
        uint32_t bBase = (uint32_t)__cvta_generic_to_shared(&Bs[st][0]);

        #pragma unroll
        for (int ks = 0; ks < 32; ks += 16) {
            uint32_t af[4][4];
            #pragma unroll
            for (int fm = 0; fm < 4; fm++)
                ldsm_x4(af[fm], aBase + ((arow + fm * 16) * SMS + ks + acol) * 2);
            uint32_t bf[4][2];
            #pragma unroll
            for (int fn = 0; fn < 4; fn++)
                ldsm_x2(bf[fn], bBase + ((brow + fn * 8) * SMS + ks + bcol) * 2);
            #pragma unroll
            for (int fm = 0; fm < 4; fm++)
                #pragma unroll
                for (int fn = 0; fn < 4; fn++)
                    mma16816(acc[fm][fn], af[fm], bf[fn]);
        }
        __syncthreads();
    }

    // --- epilogue ---
    const int head  = m0 >> 8;               // 128-tile never spans a head boundary
    const int ibase = (m0 & 255) + wm;
    const float bias = (head < 6) ? tb[head] : sb[0];

    float* sc = out + (size_t)B_ * L_ * L_ * NL_;

    #pragma unroll
    for (int fm = 0; fm < 4; fm++) {
        const int r = ibase + fm * 16 + (lane >> 2);
        #pragma unroll
        for (int fn = 0; fn < 4; fn++) {
            const int col = n0 + wn + fn * 8 + (lane & 3) * 2;
            float v00 = acc[fm][fn][0] + bias;
            float v01 = acc[fm][fn][1] + bias;
            float v10 = acc[fm][fn][2] + bias;
            float v11 = acc[fm][fn][3] + bias;
            if (head < 6) {
                float* p0 = out + (((size_t)(b * L_ + r) * L_ + col) * NL_ + head);
                p0[0] = v00; p0[NL_] = v01;
                float* p1 = out + (((size_t)(b * L_ + r + 8) * L_ + col) * NL_ + head);
                p1[0] = v10; p1[NL_] = v11;
            } else {
                float* p0 = sc + ((size_t)(b * L_ + r) * L_ + col);
                p0[0] = v00; p0[1] = v01;
                float* p1 = sc + ((size_t)(b * L_ + r + 8) * L_ + col);
                p1[0] = v10; p1[1] = v11;
            }
        }
    }
}

// ---------------------------------------------------------------------------
extern "C" void kernel_launch(void* const* d_in, const int* in_sizes, int n_in,
                              void* d_out, int out_size) {
    const int*   ids = (const int*)  d_in[0];
    const float* emb = (const float*)d_in[1];
    const float* w2  = (const float*)d_in[2];
    const float* b2  = (const float*)d_in[3];
    const float* w3  = (const float*)d_in[4];
    const float* b3  = (const float*)d_in[5];
    const float* w4  = (const float*)d_in[6];
    const float* b4  = (const float*)d_in[7];
    const float* tw  = (const float*)d_in[8];
    const float* tb  = (const float*)d_in[9];
    const float* sw  = (const float*)d_in[10];
    const float* sb  = (const float*)d_in[11];
    float* out = (float*)d_out;

    dim3 rgrid(256, 3, 1);
    reformat_w_kernel<<<rgrid, 256>>>(w2, w3, w4);

    dim3 cgrid(L_ / 64, 24, B_);          // 4 x (3 kinds * 8 f-tiles) x 4
    conv_all_kernel<<<cgrid, 256>>>(ids, emb, b2, b3, b4);

    build_ab_kernel<<<1536, 256>>>(tw, sw);

    dim3 pgrid(MSTACK_ / 128, L_ / 128, B_); // 14 x 2 x 4
    pair_mma_kernel<<<pgrid, 256>>>(tb, sb, out);
}

// round 4
// speedup vs baseline: 3.9235x; 1.7274x over previous
#include <cuda_runtime.h>
#include <cuda_bf16.h>
#include <cstdint>

// Problem constants
#define B_   4
#define L_   256
#define E_   256
#define K3_  768
#define NL_  6
#define MSTACK_ 1792   // 7 heads * 256 rows

// ---------------- scratch ----------------
__device__ __align__(16) float g_wr[589824];   // conv weights [kind][t][f][e] (e contiguous)
__device__ __align__(16) __nv_bfloat16 g_A[(size_t)B_ * MSTACK_ * K3_]; // weight-scaled feat
__device__ __align__(16) __nv_bfloat16 g_B[(size_t)B_ * L_ * K3_];      // feat bf16

#define W2OFF 0
#define W3OFF 131072
#define W4OFF 327680

// ---------------------------------------------------------------------------
// Kernel 1: reformat conv weights [f][e][t] -> [kind][t][f][e].
// ---------------------------------------------------------------------------
__global__ __launch_bounds__(256) void reformat_w_kernel(
    const float* __restrict__ w2, const float* __restrict__ w3,
    const float* __restrict__ w4)
{
    const int idx = blockIdx.x * 256 + threadIdx.x;  // 65536 over (f,e), e fastest
    const int e = idx & 255;
    const int f = idx >> 8;
    const int kind = blockIdx.y;
    const int K = kind + 2;
    const float* w = (kind == 0) ? w2 : (kind == 1) ? w3 : w4;
    const int off = (kind == 0) ? W2OFF : (kind == 1) ? W3OFF : W4OFF;
    for (int t = 0; t < K; t++)
        g_wr[off + ((t * 256 + f) * 256 + e)] = w[(f * 256 + e) * K + t];
}

// ---------------------------------------------------------------------------
// Kernel 2: conv on tensor cores (tf32 m16n8k8), fused bf16 operand build.
// CTA: 64 l x 32 f of one (batch, kind, f-tile). 8 warps: warp = 16l x 16f.
// K-loop over e in chunks of 32, 3-stage cp.async, halo'd A tile (68 rows).
// Epilogue writes g_B = bf16(feat) and g_A[h] = bf16(feat * w_h) directly.
// ---------------------------------------------------------------------------
#define A_STG (68 * 36)
#define W_STG (128 * 36)

__device__ __forceinline__ uint32_t f2tf(float x) {
    uint32_t u; asm("cvt.rna.tf32.f32 %0, %1;" : "=r"(u) : "f"(x)); return u;
}
__device__ __forceinline__ void mma_tf32(float* c, const uint32_t* a, const uint32_t* b) {
    asm volatile("mma.sync.aligned.m16n8k8.row.col.f32.tf32.tf32.f32 "
        "{%0,%1,%2,%3},{%4,%5,%6,%7},{%8,%9},{%0,%1,%2,%3};"
        : "+f"(c[0]), "+f"(c[1]), "+f"(c[2]), "+f"(c[3])
        : "r"(a[0]), "r"(a[1]), "r"(a[2]), "r"(a[3]), "r"(b[0]), "r"(b[1]));
}

template<int TAPS, int PAD>
__device__ __forceinline__ void conv_compute(
    const float* __restrict__ cA, const float* __restrict__ cW,
    int warpL, int warpF, int lane, float acc[2][4])
{
    #pragma unroll
    for (int t = 0; t < TAPS; t++) {
        #pragma unroll
        for (int ks = 0; ks < 4; ks++) {
            const int arow = warpL * 16 + (lane >> 2) + t + 1 - PAD;
            const int acol = ks * 8 + (lane & 3);
            uint32_t a[4];
            a[0] = f2tf(cA[arow * 36 + acol]);
            a[1] = f2tf(cA[(arow + 8) * 36 + acol]);
            a[2] = f2tf(cA[arow * 36 + acol + 4]);
            a[3] = f2tf(cA[(arow + 8) * 36 + acol + 4]);
            #pragma unroll
            for (int nf = 0; nf < 2; nf++) {
                const int brow = t * 32 + warpF * 16 + nf * 8 + (lane >> 2);
                uint32_t b[2];
                b[0] = f2tf(cW[brow * 36 + acol]);
                b[1] = f2tf(cW[brow * 36 + acol + 4]);
                mma_tf32(acc[nf], a, b);
            }
        }
    }
}

__global__ __launch_bounds__(256) void conv_tc_kernel(
    const int* __restrict__ ids, const float* __restrict__ emb,
    const float* __restrict__ b2, const float* __restrict__ b3,
    const float* __restrict__ b4,
    const float* __restrict__ tw, const float* __restrict__ sw)
{
    extern __shared__ __align__(16) float dsm[];
    float* sA = dsm;                 // 3 stages x 68x36
    float* sW = dsm + 3 * A_STG;     // 3 stages x 128x36
    __shared__ int   sIds[68];
    __shared__ float sTW[7][32];
    __shared__ float sBias[32];

    const int tid  = threadIdx.x;
    const int lane = tid & 31;
    const int wid  = tid >> 5;
    const int warpL = wid >> 1;      // 0..3
    const int warpF = wid & 1;       // 0..1

    const int l0   = blockIdx.x * 64;
    const int kind = blockIdx.y >> 3;
    const int ft   = blockIdx.y & 7;
    const int b    = blockIdx.z;
    const int taps = kind + 2;
    const int fbase = (kind == 0) ? 0 : (kind == 1) ? 256 : 512;
    const int woff  = (kind == 0) ? W2OFF : (kind == 1) ? W3OFF : W4OFF;
    const int kg0   = fbase + ft * 32;

    if (tid < 68) {
        int gl = l0 - 1 + tid;
        sIds[tid] = (gl >= 0 && gl < L_) ? ids[b * L_ + gl] : -1;
    }
    if (tid < 32) {
        const float* bias = (kind == 0) ? b2 : (kind == 1) ? b3 : b4;
        sBias[tid] = bias[ft * 32 + tid];
        #pragma unroll
        for (int h = 0; h < 7; h++)
            sTW[h][tid] = (h < 6) ? tw[h * K3_ + kg0 + tid] : sw[kg0 + tid];
    }
    __syncthreads();

    auto load_chunk = [&](int c) {
        const int stg = c % 3;
        const int e0  = c * 32;
        float* dA = sA + stg * A_STG;
        for (int idx = tid; idx < 68 * 8; idx += 256) {
            int row = idx >> 3, q = idx & 7;
            uint32_t dst = (uint32_t)__cvta_generic_to_shared(dA + row * 36 + q * 4);
            int id = sIds[row];
            const float* src = emb + (size_t)max(id, 0) * E_ + e0 + q * 4;
            uint32_t sz = (id >= 0) ? 16u : 0u;
            asm volatile("cp.async.cg.shared.global [%0], [%1], 16, %2;"
                :: "r"(dst), "l"(src), "r"(sz));
        }
        float* dW = sW + stg * W_STG;
        for (int idx = tid; idx < taps * 32 * 8; idx += 256) {
            int row = idx >> 3, q = idx & 7;      // row = t*32 + f
            int t = row >> 5, f = row & 31;
            uint32_t dst = (uint32_t)__cvta_generic_to_shared(dW + row * 36 + q * 4);
            const float* src = g_wr + woff + ((t * 256 + ft * 32 + f) * 256 + e0 + q * 4);
            asm volatile("cp.async.cg.shared.global [%0], [%1], 16;"
                :: "r"(dst), "l"(src));
        }
        asm volatile("cp.async.commit_group;");
    };

    float acc[2][4] = {};

    load_chunk(0);
    load_chunk(1);

    for (int c = 0; c < 8; c++) {
        if (c < 7) asm volatile("cp.async.wait_group 1;");
        else       asm volatile("cp.async.wait_group 0;");
        __syncthreads();
        if (c + 2 < 8) load_chunk(c + 2);
        const float* cA = sA + (c % 3) * A_STG;
        const float* cW = sW + (c % 3) * W_STG;
        if (taps == 2)      conv_compute<2, 0>(cA, cW, warpL, warpF, lane, acc);
        else if (taps == 3) conv_compute<3, 1>(cA, cW, warpL, warpF, lane, acc);
        else                conv_compute<4, 1>(cA, cW, warpL, warpF, lane, acc);
    }

    // --- fused epilogue: bias + bf16 operand build ---
    #pragma unroll
    for (int nf = 0; nf < 2; nf++) {
        const int fl = warpF * 16 + nf * 8 + (lane & 3) * 2;
        const int kg = kg0 + fl;
        const float bb0 = sBias[fl], bb1 = sBias[fl + 1];
        #pragma unroll
        for (int half = 0; half < 2; half++) {
            const int l = l0 + warpL * 16 + half * 8 + (lane >> 2);
            const float v0 = acc[nf][half * 2 + 0] + bb0;
            const float v1 = acc[nf][half * 2 + 1] + bb1;
            *reinterpret_cast<__nv_bfloat162*>(
                &g_B[((size_t)(b * L_ + l)) * K3_ + kg]) =
                __floats2bfloat162_rn(v0, v1);
            #pragma unroll
            for (int h = 0; h < 7; h++) {
                const float s0 = sTW[h][fl], s1 = sTW[h][fl + 1];
                *reinterpret_cast<__nv_bfloat162*>(
                    &g_A[((size_t)b * MSTACK_ + h * 256 + l) * K3_ + kg]) =
                    __floats2bfloat162_rn(v0 * s0, v1 * s1);
            }
        }
    }
}

// ---------------------------------------------------------------------------
// Kernel 3: pair GEMM (bf16 mma.m16n8k16), 4-stage cp.async, 1 sync/iter.
//   per batch: C[1792, 256] = A[1792, 768] * B[256, 768]^T
// ---------------------------------------------------------------------------
__device__ __forceinline__ void ldsm_x4(uint32_t* r, uint32_t addr) {
    asm volatile("ldmatrix.sync.aligned.m8n8.x4.shared.b16 {%0,%1,%2,%3}, [%4];"
        : "=r"(r[0]), "=r"(r[1]), "=r"(r[2]), "=r"(r[3]) : "r"(addr));
}
__device__ __forceinline__ void ldsm_x2(uint32_t* r, uint32_t addr) {
    asm volatile("ldmatrix.sync.aligned.m8n8.x2.shared.b16 {%0,%1}, [%2];"
        : "=r"(r[0]), "=r"(r[1]) : "r"(addr));
}
__device__ __forceinline__ void mma16816(float* c, const uint32_t* a, const uint32_t* b) {
    asm volatile("mma.sync.aligned.m16n8k16.row.col.f32.bf16.bf16.f32 "
        "{%0,%1,%2,%3}, {%4,%5,%6,%7}, {%8,%9}, {%0,%1,%2,%3};"
        : "+f"(c[0]), "+f"(c[1]), "+f"(c[2]), "+f"(c[3])
        : "r"(a[0]), "r"(a[1]), "r"(a[2]), "r"(a[3]), "r"(b[0]), "r"(b[1]));
}

#define SMS 40   // smem row stride (bf16): 32 payload + 8 pad
#define PSTG (128 * SMS)

__global__ __launch_bounds__(256) void pair_mma_kernel(
    const float* __restrict__ tb, const float* __restrict__ sb,
    float* __restrict__ out)
{
    extern __shared__ __align__(16) __nv_bfloat16 psm[];
    __nv_bfloat16* As = psm;              // 4 stages x 128*SMS
    __nv_bfloat16* Bs = psm + 4 * PSTG;   // 4 stages x 128*SMS

    const int tid  = threadIdx.x;
    const int lane = tid & 31;
    const int wid  = tid >> 5;
    const int wm   = (wid >> 2) * 64;
    const int wn   = (wid & 3) * 32;

    const int b  = blockIdx.z;
    const int m0 = blockIdx.x * 128;
    const int n0 = blockIdx.y * 128;

    const __nv_bfloat16* gA = g_A + ((size_t)b * MSTACK_ + m0) * K3_;
    const __nv_bfloat16* gB = g_B + ((size_t)b * L_ + n0) * K3_;

    float acc[4][4][4] = {};

    const int lrow = tid >> 2;
    const int lq   = tid & 3;

    auto load_stage = [&](int stage, int k0) {
        #pragma unroll
        for (int it = 0; it < 2; it++) {
            int row = lrow + it * 64;
            uint32_t sA = (uint32_t)__cvta_generic_to_shared(
                &As[stage * PSTG + row * SMS + lq * 8]);
            const void* pA = gA + (size_t)row * K3_ + k0 + lq * 8;
            asm volatile("cp.async.cg.shared.global [%0], [%1], 16;" :: "r"(sA), "l"(pA));
            uint32_t sB = (uint32_t)__cvta_generic_to_shared(
                &Bs[stage * PSTG + row * SMS + lq * 8]);
            const void* pB = gB + (size_t)row * K3_ + k0 + lq * 8;
            asm volatile("cp.async.cg.shared.global [%0], [%1], 16;" :: "r"(sB), "l"(pB));
        }
        asm volatile("cp.async.commit_group;");
    };

    load_stage(0, 0);
    load_stage(1, 32);
    load_stage(2, 64);

    const int arow = wm + (lane & 15);
    const int acol = (lane >> 4) * 8;
    const int brow = wn + (lane & 7);
    const int bcol = ((lane >> 3) & 1) * 8;

    for (int it = 0; it < 24; it++) {
        if (it < 22)      asm volatile("cp.async.wait_group 2;");
        else if (it == 22) asm volatile("cp.async.wait_group 1;");
        else              asm volatile("cp.async.wait_group 0;");
        __syncthreads();

        if (it + 3 < 24) load_stage((it + 3) & 3, (it + 3) * 32);

        const int st = it & 3;
        uint32_t aBase = (uint32_t)__cvta_generic_to_shared(&As[st * PSTG]);
        uint32_t bBase = (uint32_t)__cvta_generic_to_shared(&Bs[st * PSTG]);

        #pragma unroll
        for (int ks = 0; ks < 32; ks += 16) {
            uint32_t af[4][4];
            #pragma unroll
            for (int fm = 0; fm < 4; fm++)
                ldsm_x4(af[fm], aBase + ((arow + fm * 16) * SMS + ks + acol) * 2);
            uint32_t bf[4][2];
            #pragma unroll
            for (int fn = 0; fn < 4; fn++)
                ldsm_x2(bf[fn], bBase + ((brow + fn * 8) * SMS + ks + bcol) * 2);
            #pragma unroll
            for (int fm = 0; fm < 4; fm++)
                #pragma unroll
                for (int fn = 0; fn < 4; fn++)
                    mma16816(acc[fm][fn], af[fm], bf[fn]);
        }
    }

    // --- epilogue ---
    const int head  = m0 >> 8;
    const int ibase = (m0 & 255) + wm;
    const float bias = (head < 6) ? tb[head] : sb[0];

    float* sc = out + (size_t)B_ * L_ * L_ * NL_;

    #pragma unroll
    for (int fm = 0; fm < 4; fm++) {
        const int r = ibase + fm * 16 + (lane >> 2);
        #pragma unroll
        for (int fn = 0; fn < 4; fn++) {
            const int col = n0 + wn + fn * 8 + (lane & 3) * 2;
            float v00 = acc[fm][fn][0] + bias;
            float v01 = acc[fm][fn][1] + bias;
            float v10 = acc[fm][fn][2] + bias;
            float v11 = acc[fm][fn][3] + bias;
            if (head < 6) {
                float* p0 = out + (((size_t)(b * L_ + r) * L_ + col) * NL_ + head);
                p0[0] = v00; p0[NL_] = v01;
                float* p1 = out + (((size_t)(b * L_ + r + 8) * L_ + col) * NL_ + head);
                p1[0] = v10; p1[NL_] = v11;
            } else {
                float* p0 = sc + ((size_t)(b * L_ + r) * L_ + col);
                p0[0] = v00; p0[1] = v01;
                float* p1 = sc + ((size_t)(b * L_ + r + 8) * L_ + col);
                p1[0] = v10; p1[1] = v11;
            }
        }
    }
}

// ---------------------------------------------------------------------------
extern "C" void kernel_launch(void* const* d_in, const int* in_sizes, int n_in,
                              void* d_out, int out_size) {
    const int*   ids = (const int*)  d_in[0];
    const float* emb = (const float*)d_in[1];
    const float* w2  = (const float*)d_in[2];
    const float* b2  = (const float*)d_in[3];
    const float* w3  = (const float*)d_in[4];
    const float* b3  = (const float*)d_in[5];
    const float* w4  = (const float*)d_in[6];
    const float* b4  = (const float*)d_in[7];
    const float* tw  = (const float*)d_in[8];
    const float* tb  = (const float*)d_in[9];
    const float* sw  = (const float*)d_in[10];
    const float* sb  = (const float*)d_in[11];
    float* out = (float*)d_out;

    const int conv_smem = 3 * (A_STG + W_STG) * 4;      // 84,672 B
    const int pair_smem = 8 * PSTG * 2;                 // 81,920 B
    cudaFuncSetAttribute(conv_tc_kernel,
        cudaFuncAttributeMaxDynamicSharedMemorySize, conv_smem);
    cudaFuncSetAttribute(pair_mma_kernel,
        cudaFuncAttributeMaxDynamicSharedMemorySize, pair_smem);

    dim3 rgrid(256, 3, 1);
    reformat_w_kernel<<<rgrid, 256>>>(w2, w3, w4);

    dim3 cgrid(4, 24, 4);   // l-tiles x (kind*8 + f-tile) x batch = 384 CTAs
    conv_tc_kernel<<<cgrid, 256, conv_smem>>>(ids, emb, b2, b3, b4, tw, sw);

    dim3 pgrid(MSTACK_ / 128, L_ / 128, B_);  // 14 x 2 x 4 = 112 CTAs
    pair_mma_kernel<<<pgrid, 256, pair_smem>>>(tb, sb, out);
}

// round 5
// speedup vs baseline: 4.2436x; 1.0816x over previous
#include <cuda_runtime.h>
#include <cuda_bf16.h>
#include <cstdint>

// Problem constants
#define B_   4
#define L_   256
#define E_   256
#define K3_  768
#define NL_  6
#define MPAD_ 2048   // 8 heads (7 real + 1 zero pad) * 256 rows, row = i*8 + h

// ---------------- scratch ----------------
__device__ __align__(16) __nv_bfloat16 g_A[(size_t)B_ * MPAD_ * K3_]; // head-interleaved
__device__ __align__(16) __nv_bfloat16 g_B[(size_t)B_ * L_ * K3_];

// ---------------------------------------------------------------------------
// Conv on tensor cores (tf32 m16n8k8), fused bf16 operand build.
// CTA: 64 l x 32 f of one (batch, kind, f-tile). 8 warps = 4(L) x 2(F).
// e-chunks of 32, 3-stage cp.async. Weights loaded directly from the original
// [f][e][t] layout with 4B cp.async (transpose into smem).
// Epilogue: stage C in smem, then dense k-contiguous STG.128 of g_B and
// g_A[h] for h=0..7 (h=7 scale 0).
// ---------------------------------------------------------------------------
#define A_STG (68 * 36)
#define W_STG (128 * 36)

__device__ __forceinline__ uint32_t f2tf(float x) {
    uint32_t u; asm("cvt.rna.tf32.f32 %0, %1;" : "=r"(u) : "f"(x)); return u;
}
__device__ __forceinline__ void mma_tf32(float* c, const uint32_t* a, const uint32_t* b) {
    asm volatile("mma.sync.aligned.m16n8k8.row.col.f32.tf32.tf32.f32 "
        "{%0,%1,%2,%3},{%4,%5,%6,%7},{%8,%9},{%0,%1,%2,%3};"
        : "+f"(c[0]), "+f"(c[1]), "+f"(c[2]), "+f"(c[3])
        : "r"(a[0]), "r"(a[1]), "r"(a[2]), "r"(a[3]), "r"(b[0]), "r"(b[1]));
}

template<int TAPS, int PAD>
__device__ __forceinline__ void conv_compute(
    const float* __restrict__ cA, const float* __restrict__ cW,
    int warpL, int warpF, int lane, float acc[2][4])
{
    #pragma unroll
    for (int t = 0; t < TAPS; t++) {
        #pragma unroll
        for (int ks = 0; ks < 4; ks++) {
            const int arow = warpL * 16 + (lane >> 2) + t + 1 - PAD;
            const int acol = ks * 8 + (lane & 3);
            uint32_t a[4];
            a[0] = f2tf(cA[arow * 36 + acol]);
            a[1] = f2tf(cA[(arow + 8) * 36 + acol]);
            a[2] = f2tf(cA[arow * 36 + acol + 4]);
            a[3] = f2tf(cA[(arow + 8) * 36 + acol + 4]);
            #pragma unroll
            for (int nf = 0; nf < 2; nf++) {
                const int brow = t * 32 + warpF * 16 + nf * 8 + (lane >> 2);
                uint32_t b[2];
                b[0] = f2tf(cW[brow * 36 + acol]);
                b[1] = f2tf(cW[brow * 36 + acol + 4]);
                mma_tf32(acc[nf], a, b);
            }
        }
    }
}

__global__ __launch_bounds__(256) void conv_tc_kernel(
    const int* __restrict__ ids, const float* __restrict__ emb,
    const float* __restrict__ w2, const float* __restrict__ w3,
    const float* __restrict__ w4,
    const float* __restrict__ b2, const float* __restrict__ b3,
    const float* __restrict__ b4,
    const float* __restrict__ tw, const float* __restrict__ sw)
{
    extern __shared__ __align__(16) float dsm[];
    float* sA = dsm;                 // 3 stages x 68x36
    float* sW = dsm + 3 * A_STG;     // 3 stages x 128x36
    __shared__ int   sIds[68];
    __shared__ float sTW[8][32];
    __shared__ float sBias[32];

    const int tid  = threadIdx.x;
    const int lane = tid & 31;
    const int wid  = tid >> 5;
    const int warpL = wid >> 1;      // 0..3
    const int warpF = wid & 1;       // 0..1

    const int l0   = blockIdx.x * 64;
    const int kind = blockIdx.y >> 3;
    const int ft   = blockIdx.y & 7;
    const int b    = blockIdx.z;
    const int taps = kind + 2;
    const int fbase = (kind == 0) ? 0 : (kind == 1) ? 256 : 512;
    const float* __restrict__ w = (kind == 0) ? w2 : (kind == 1) ? w3 : w4;
    const int kg0   = fbase + ft * 32;

    if (tid < 68) {
        int gl = l0 - 1 + tid;
        sIds[tid] = (gl >= 0 && gl < L_) ? ids[b * L_ + gl] : -1;
    }
    if (tid < 32) {
        const float* bias = (kind == 0) ? b2 : (kind == 1) ? b3 : b4;
        sBias[tid] = bias[ft * 32 + tid];
        #pragma unroll
        for (int h = 0; h < 8; h++)
            sTW[h][tid] = (h < 6) ? tw[h * K3_ + kg0 + tid]
                        : (h == 6) ? sw[kg0 + tid] : 0.0f;
    }
    __syncthreads();

    auto load_chunk = [&](int c) {
        const int stg = c % 3;
        const int e0  = c * 32;
        float* dA = sA + stg * A_STG;
        for (int idx = tid; idx < 68 * 8; idx += 256) {
            int row = idx >> 3, q = idx & 7;
            uint32_t dst = (uint32_t)__cvta_generic_to_shared(dA + row * 36 + q * 4);
            int id = sIds[row];
            const float* src = emb + (size_t)max(id, 0) * E_ + e0 + q * 4;
            uint32_t sz = (id >= 0) ? 16u : 0u;
            asm volatile("cp.async.cg.shared.global [%0], [%1], 16, %2;"
                :: "r"(dst), "l"(src), "r"(sz));
        }
        float* dW = sW + stg * W_STG;
        for (int idx = tid; idx < taps * 1024; idx += 256) {
            int ep = idx & 31;
            int f  = (idx >> 5) & 31;
            int t  = idx >> 10;
            uint32_t dst = (uint32_t)__cvta_generic_to_shared(
                dW + (t * 32 + f) * 36 + ep);
            const float* src = w + ((size_t)(ft * 32 + f) * 256 + e0 + ep) * taps + t;
            asm volatile("cp.async.ca.shared.global [%0], [%1], 4;"
                :: "r"(dst), "l"(src));
        }
        asm volatile("cp.async.commit_group;");
    };

    float acc[2][4] = {};

    load_chunk(0);
    load_chunk(1);

    for (int c = 0; c < 8; c++) {
        if (c < 7) asm volatile("cp.async.wait_group 1;");
        else       asm volatile("cp.async.wait_group 0;");
        __syncthreads();
        if (c + 2 < 8) load_chunk(c + 2);
        const float* cA = sA + (c % 3) * A_STG;
        const float* cW = sW + (c % 3) * W_STG;
        if (taps == 2)      conv_compute<2, 0>(cA, cW, warpL, warpF, lane, acc);
        else if (taps == 3) conv_compute<3, 1>(cA, cW, warpL, warpF, lane, acc);
        else                conv_compute<4, 1>(cA, cW, warpL, warpF, lane, acc);
    }

    // --- epilogue: stage C in smem (stride 40), then dense stores ---
    __syncthreads();                 // pipeline fully consumed; reuse dsm
    float* Cs = dsm;                 // [64][40]
    #pragma unroll
    for (int nf = 0; nf < 2; nf++) {
        const int col = warpF * 16 + nf * 8 + (lane & 3) * 2;
        #pragma unroll
        for (int half = 0; half < 2; half++) {
            const int row = warpL * 16 + (lane >> 2) + half * 8;
            *reinterpret_cast<float2*>(&Cs[row * 40 + col]) =
                make_float2(acc[nf][half * 2 + 0], acc[nf][half * 2 + 1]);
        }
    }
    __syncthreads();

    const int row = tid >> 2;            // 0..63 (l local)
    const int c8  = (tid & 3) * 8;       // f-local base
    float f[8];
    *reinterpret_cast<float4*>(f)     = *reinterpret_cast<float4*>(&Cs[row * 40 + c8]);
    *reinterpret_cast<float4*>(f + 4) = *reinterpret_cast<float4*>(&Cs[row * 40 + c8 + 4]);
    float v[8];
    #pragma unroll
    for (int q = 0; q < 8; q++) v[q] = f[q] + sBias[c8 + q];

    // g_B: dense 16B store
    {
        __nv_bfloat162 p[4];
        #pragma unroll
        for (int q = 0; q < 4; q++)
            p[q] = __floats2bfloat162_rn(v[2 * q], v[2 * q + 1]);
        *reinterpret_cast<uint4*>(
            &g_B[((size_t)(b * L_ + l0 + row)) * K3_ + kg0 + c8]) =
            *reinterpret_cast<uint4*>(p);
    }
    // g_A heads 0..7 (7 = zero pad): dense 16B stores
    #pragma unroll
    for (int h = 0; h < 8; h++) {
        __nv_bfloat162 p[4];
        #pragma unroll
        for (int q = 0; q < 4; q++)
            p[q] = __floats2bfloat162_rn(v[2 * q] * sTW[h][c8 + 2 * q],
                                         v[2 * q + 1] * sTW[h][c8 + 2 * q + 1]);
        *reinterpret_cast<uint4*>(
            &g_A[((size_t)b * MPAD_ + (size_t)(l0 + row) * 8 + h) * K3_ + kg0 + c8]) =
            *reinterpret_cast<uint4*>(p);
    }
}

// ---------------------------------------------------------------------------
// Pair GEMM (bf16 mma.m16n8k16): per batch C[2048, 256] = A * B^T, A rows
// head-interleaved (row = i*8 + h). CTA tile 128m x 64n, 8 warps = 4(M) x 2(N),
// warp tile 32x32. 4-stage cp.async. Epilogue stages C in smem and writes the
// [i][j][head] output densely.
// ---------------------------------------------------------------------------
__device__ __forceinline__ void ldsm_x4(uint32_t* r, uint32_t addr) {
    asm volatile("ldmatrix.sync.aligned.m8n8.x4.shared.b16 {%0,%1,%2,%3}, [%4];"
        : "=r"(r[0]), "=r"(r[1]), "=r"(r[2]), "=r"(r[3]) : "r"(addr));
}
__device__ __forceinline__ void ldsm_x2(uint32_t* r, uint32_t addr) {
    asm volatile("ldmatrix.sync.aligned.m8n8.x2.shared.b16 {%0,%1}, [%2];"
        : "=r"(r[0]), "=r"(r[1]) : "r"(addr));
}
__device__ __forceinline__ void mma16816(float* c, const uint32_t* a, const uint32_t* b) {
    asm volatile("mma.sync.aligned.m16n8k16.row.col.f32.bf16.bf16.f32 "
        "{%0,%1,%2,%3}, {%4,%5,%6,%7}, {%8,%9}, {%0,%1,%2,%3};"
        : "+f"(c[0]), "+f"(c[1]), "+f"(c[2]), "+f"(c[3])
        : "r"(a[0]), "r"(a[1]), "r"(a[2]), "r"(a[3]), "r"(b[0]), "r"(b[1]));
}

#define SMS 40                 // smem k-stride (bf16): 32 payload + 8 pad
#define PA_STG (128 * SMS)     // A stage
#define PB_STG (64 * SMS)      // B stage

__global__ __launch_bounds__(256) void pair_mma_kernel(
    const float* __restrict__ tb, const float* __restrict__ sb,
    float* __restrict__ out)
{
    extern __shared__ __align__(16) __nv_bfloat16 psm[];
    __nv_bfloat16* As = psm;                   // 4 stages x 128*SMS
    __nv_bfloat16* Bs = psm + 4 * PA_STG;      // 4 stages x 64*SMS

    const int tid  = threadIdx.x;
    const int lane = tid & 31;
    const int wid  = tid >> 5;
    const int wm   = (wid >> 1) * 32;   // 0,32,64,96
    const int wn   = (wid & 1) * 32;    // 0,32

    const int b  = blockIdx.z;
    const int m0 = blockIdx.x * 128;    // over 2048 (i0 = m0/8)
    const int n0 = blockIdx.y * 64;

    const __nv_bfloat16* gA = g_A + ((size_t)b * MPAD_ + m0) * K3_;
    const __nv_bfloat16* gB = g_B + ((size_t)b * L_ + n0) * K3_;

    float acc[2][4][4] = {};

    const int lrow = tid >> 2;
    const int lq   = tid & 3;

    auto load_stage = [&](int stage, int k0) {
        #pragma unroll
        for (int it = 0; it < 2; it++) {
            int row = lrow + it * 64;
            uint32_t sA = (uint32_t)__cvta_generic_to_shared(
                &As[stage * PA_STG + row * SMS + lq * 8]);
            const void* pA = gA + (size_t)row * K3_ + k0 + lq * 8;
            asm volatile("cp.async.cg.shared.global [%0], [%1], 16;" :: "r"(sA), "l"(pA));
        }
        uint32_t sB = (uint32_t)__cvta_generic_to_shared(
            &Bs[stage * PB_STG + lrow * SMS + lq * 8]);
        const void* pB = gB + (size_t)lrow * K3_ + k0 + lq * 8;
        asm volatile("cp.async.cg.shared.global [%0], [%1], 16;" :: "r"(sB), "l"(pB));
        asm volatile("cp.async.commit_group;");
    };

    load_stage(0, 0);
    load_stage(1, 32);
    load_stage(2, 64);

    const int arow = wm + (lane & 15);
    const int acol = (lane >> 4) * 8;
    const int brow = wn + (lane & 7);
    const int bcol = ((lane >> 3) & 1) * 8;

    for (int it = 0; it < 24; it++) {
        if (it < 22)       asm volatile("cp.async.wait_group 2;");
        else if (it == 22) asm volatile("cp.async.wait_group 1;");
        else               asm volatile("cp.async.wait_group 0;");
        __syncthreads();

        if (it + 3 < 24) load_stage((it + 3) & 3, (it + 3) * 32);

        const int st = it & 3;
        uint32_t aBase = (uint32_t)__cvta_generic_to_shared(&As[st * PA_STG]);
        uint32_t bBase = (uint32_t)__cvta_generic_to_shared(&Bs[st * PB_STG]);

        #pragma unroll
        for (int ks = 0; ks < 32; ks += 16) {
            uint32_t af[2][4];
            #pragma unroll
            for (int fm = 0; fm < 2; fm++)
                ldsm_x4(af[fm], aBase + ((arow + fm * 16) * SMS + ks + acol) * 2);
            uint32_t bf[4][2];
            #pragma unroll
            for (int fn = 0; fn < 4; fn++)
                ldsm_x2(bf[fn], bBase + ((brow + fn * 8) * SMS + ks + bcol) * 2);
            #pragma unroll
            for (int fm = 0; fm < 2; fm++)
                #pragma unroll
                for (int fn = 0; fn < 4; fn++)
                    mma16816(acc[fm][fn], af[fm], bf[fn]);
        }
    }

    // --- epilogue: stage C tile [128][72] in smem, then dense output ---
    __syncthreads();
    float* Cs = reinterpret_cast<float*>(psm);    // 128*72*4 = 36,864 B
    #pragma unroll
    for (int fm = 0; fm < 2; fm++) {
        #pragma unroll
        for (int fn = 0; fn < 4; fn++) {
            const int r0 = wm + fm * 16 + (lane >> 2);
            const int c0 = wn + fn * 8 + (lane & 3) * 2;
            *reinterpret_cast<float2*>(&Cs[r0 * 72 + c0]) =
                make_float2(acc[fm][fn][0], acc[fm][fn][1]);
            *reinterpret_cast<float2*>(&Cs[(r0 + 8) * 72 + c0]) =
                make_float2(acc[fm][fn][2], acc[fm][fn][3]);
        }
    }
    __syncthreads();

    float bb[6];
    #pragma unroll
    for (int h = 0; h < 6; h++) bb[h] = tb[h];
    const float sb0 = sb[0];

    const int i0 = m0 >> 3;    // 16 i values per tile

    // triple logits: 16 i x 64 j x 6 heads = 3072 float2, 12 per thread
    #pragma unroll
    for (int r = 0; r < 12; r++) {
        const int fidx = tid + r * 256;
        const int i    = fidx / 192;
        const int o    = (fidx % 192) * 2;          // float offset in row block
        const int j0l  = o / 6,       h0l = o - j0l * 6;
        const int j1l  = (o + 1) / 6, h1l = (o + 1) - j1l * 6;
        float2 vv;
        vv.x = Cs[(i * 8 + h0l) * 72 + j0l] + bb[h0l];
        vv.y = Cs[(i * 8 + h1l) * 72 + j1l] + bb[h1l];
        *reinterpret_cast<float2*>(
            out + ((size_t)((b * L_ + i0 + i) * L_ + n0)) * NL_ + o) = vv;
    }

    // scores: 16 i x 64 j = 256 float4, 1 per thread
    {
        float* sc = out + (size_t)B_ * L_ * L_ * NL_;
        const int i  = tid >> 4;
        const int j4 = (tid & 15) * 4;
        float4 vv;
        vv.x = Cs[(i * 8 + 6) * 72 + j4 + 0] + sb0;
        vv.y = Cs[(i * 8 + 6) * 72 + j4 + 1] + sb0;
        vv.z = Cs[(i * 8 + 6) * 72 + j4 + 2] + sb0;
        vv.w = Cs[(i * 8 + 6) * 72 + j4 + 3] + sb0;
        *reinterpret_cast<float4*>(
            sc + (size_t)(b * L_ + i0 + i) * L_ + n0 + j4) = vv;
    }
}

// ---------------------------------------------------------------------------
extern "C" void kernel_launch(void* const* d_in, const int* in_sizes, int n_in,
                              void* d_out, int out_size) {
    const int*   ids = (const int*)  d_in[0];
    const float* emb = (const float*)d_in[1];
    const float* w2  = (const float*)d_in[2];
    const float* b2  = (const float*)d_in[3];
    const float* w3  = (const float*)d_in[4];
    const float* b3  = (const float*)d_in[5];
    const float* w4  = (const float*)d_in[6];
    const float* b4  = (const float*)d_in[7];
    const float* tw  = (const float*)d_in[8];
    const float* tb  = (const float*)d_in[9];
    const float* sw  = (const float*)d_in[10];
    const float* sb  = (const float*)d_in[11];
    float* out = (float*)d_out;

    const int conv_smem = 3 * (A_STG + W_STG) * 4;              // 84,672 B
    const int pair_smem = 4 * (PA_STG + PB_STG) * 2;            // 61,440 B
    cudaFuncSetAttribute(conv_tc_kernel,
        cudaFuncAttributeMaxDynamicSharedMemorySize, conv_smem);
    cudaFuncSetAttribute(pair_mma_kernel,
        cudaFuncAttributeMaxDynamicSharedMemorySize, pair_smem);

    dim3 cgrid(4, 24, 4);   // l-tiles x (kind*8 + f-tile) x batch = 384 CTAs
    conv_tc_kernel<<<cgrid, 256, conv_smem>>>(ids, emb, w2, w3, w4,
                                              b2, b3, b4, tw, sw);

    dim3 pgrid(MPAD_ / 128, L_ / 64, B_);  // 16 x 4 x 4 = 256 CTAs
    pair_mma_kernel<<<pgrid, 256, pair_smem>>>(tb, sb, out);
}